// round 1
// baseline (speedup 1.0000x reference)
#include <cuda_runtime.h>
#include <math.h>

#define VSZ 32000
#define ESZ 512
#define HSZ 1024
#define SSZ 64
#define TSZ 64
#define BSZ 32
#define HB  (HSZ*BSZ)
#define PAD_IDX 1
#define NEGV -100000.0f

// ---------------- device scratch (no allocations allowed) ----------------
__device__ float g_emb_src[SSZ*ESZ*BSZ];    // [s][e][b]
__device__ float g_enc_out_t[SSZ*BSZ*HSZ];  // [s][b][k]
__device__ float g_h0[2*HB];                // [k][b] double buffered
__device__ float g_h1[2*HB];
__device__ float g_dh0[2*HB];
__device__ float g_dh1[2*HB];
__device__ float g_h1t[BSZ*HSZ];            // [b][k]
__device__ float g_ctx_t[BSZ*HSZ];          // [b][k]
__device__ float g_cc_t[BSZ*HSZ];           // [b][k]

// ---------------- small utility kernels ----------------
__global__ void zero_kernel(float* p, int n) {
    for (int i = blockIdx.x*blockDim.x + threadIdx.x; i < n; i += gridDim.x*blockDim.x)
        p[i] = 0.f;
}

// out[s][e][b] = emb[tok[s][b]][e]
__global__ void embed_kernel(const int* __restrict__ tok,
                             const float* __restrict__ emb,
                             float* __restrict__ out) {
    int idx = blockIdx.x*256 + threadIdx.x;          // S*E*B total
    int b = idx & 31;
    int e = (idx >> 5) & (ESZ-1);
    int s = idx >> 14;                               // 5+9
    out[idx] = emb[(size_t)tok[s*BSZ + b]*ESZ + e];
}

// ---------------- fused GRU cell ----------------
// Each warp computes one output unit j for all 32 batch lanes.
// Activations come through an smem tile so they are loaded once per block.
__device__ __forceinline__ void gru_dots(
    const float* __restrict__ src,   // [K][B] (ignored if tok != null)
    const int*   __restrict__ tok,   // [B] token ids, or null
    const float* __restrict__ emb,   // [V][K] embedding table (gather path)
    int K,
    const float* __restrict__ w0, const float* __restrict__ w1,
    const float* __restrict__ w2,
    float* Xs, int w, int lane,
    float& s0, float& s1, float& s2)
{
    for (int k0 = 0; k0 < K; k0 += 128) {
        __syncthreads();
        if (tok) {
            // gather path: lanes run along k (coalesced along embedding row)
            #pragma unroll
            for (int r = 0; r < 4; r++) {
                #pragma unroll
                for (int bb = 0; bb < 4; bb++) {
                    int b  = w + bb*8;
                    int kk = lane + r*32;
                    Xs[kk*36 + b] = emb[(size_t)tok[b]*K + k0 + kk];
                }
            }
        } else {
            // [K][B] path: lanes run along b, float4
            int bg  = threadIdx.x & 7;
            int kkb = threadIdx.x >> 3;
            #pragma unroll
            for (int i2 = 0; i2 < 4; i2++) {
                int kk = kkb + 32*i2;
                *(float4*)(Xs + kk*36 + bg*4) =
                    *(const float4*)(src + (size_t)(k0+kk)*BSZ + bg*4);
            }
        }
        __syncthreads();
        #pragma unroll 8
        for (int q = 0; q < 32; q++) {
            float4 a  = *(const float4*)(w0 + k0 + q*4);
            float4 bz = *(const float4*)(w1 + k0 + q*4);
            float4 cn = *(const float4*)(w2 + k0 + q*4);
            float x0 = Xs[(q*4+0)*36 + lane];
            float x1 = Xs[(q*4+1)*36 + lane];
            float x2 = Xs[(q*4+2)*36 + lane];
            float x3 = Xs[(q*4+3)*36 + lane];
            s0 += a.x*x0  + a.y*x1  + a.z*x2  + a.w*x3;
            s1 += bz.x*x0 + bz.y*x1 + bz.z*x2 + bz.w*x3;
            s2 += cn.x*x0 + cn.y*x1 + cn.z*x2 + cn.w*x3;
        }
    }
}

__global__ __launch_bounds__(256) void gru_cell_kernel(
    const float* __restrict__ x, int Kx,            // x layout [Kx][B]
    const int*   __restrict__ tok,                  // or gather from emb
    const float* __restrict__ emb,
    const float* __restrict__ h_old,                // [H][B]
    const float* __restrict__ Wih,                  // [3H][Kx]
    const float* __restrict__ Whh,                  // [3H][H]
    const float* __restrict__ bih,
    const float* __restrict__ bhh,
    float* __restrict__ h_new,                      // [H][B]
    float* __restrict__ out_t)                      // [B][H] or null
{
    __shared__ float Xs[128*36];
    int w = threadIdx.x >> 5, lane = threadIdx.x & 31;
    int j = blockIdx.x*8 + w;

    float xr = 0.f, xz = 0.f, xn = 0.f;
    gru_dots(x, tok, emb, Kx,
             Wih + (size_t)j*Kx,
             Wih + (size_t)(HSZ   + j)*Kx,
             Wih + (size_t)(2*HSZ + j)*Kx,
             Xs, w, lane, xr, xz, xn);

    float hr = 0.f, hz = 0.f, hn = 0.f;
    gru_dots(h_old, nullptr, nullptr, HSZ,
             Whh + (size_t)j*HSZ,
             Whh + (size_t)(HSZ   + j)*HSZ,
             Whh + (size_t)(2*HSZ + j)*HSZ,
             Xs, w, lane, hr, hz, hn);

    float gr = xr + bih[j]       + hr + bhh[j];
    float gz = xz + bih[HSZ+j]   + hz + bhh[HSZ+j];
    float r  = 1.f/(1.f + expf(-gr));
    float z  = 1.f/(1.f + expf(-gz));
    float n  = tanhf(xn + bih[2*HSZ+j] + r*(hn + bhh[2*HSZ+j]));
    float hp = h_old[j*BSZ + lane];
    float hv = (1.f - z)*n + z*hp;
    h_new[j*BSZ + lane] = hv;
    if (out_t) out_t[(size_t)lane*HSZ + j] = hv;
}

// ---------------- attention (one block per batch element) ----------------
__global__ __launch_bounds__(256) void attn_kernel(
    const float* __restrict__ h1t,        // [B][H]
    const float* __restrict__ enc_out_t,  // [S][B][H]
    const int*   __restrict__ src_tokens, // [S][B]
    float* __restrict__ ctx_t)            // [B][H]
{
    int b = blockIdx.x;
    int w = threadIdx.x >> 5, lane = threadIdx.x & 31;
    __shared__ float sc[64];

    // preload query (row b of h1t)
    float4 q[8];
    #pragma unroll
    for (int c = 0; c < 8; c++)
        q[c] = *(const float4*)(h1t + (size_t)b*HSZ + c*128 + lane*4);

    #pragma unroll
    for (int i = 0; i < 8; i++) {
        int s = w*8 + i;
        const float* e = enc_out_t + ((size_t)s*BSZ + b)*HSZ;
        float acc = 0.f;
        #pragma unroll
        for (int c = 0; c < 8; c++) {
            float4 ev = *(const float4*)(e + c*128 + lane*4);
            acc += q[c].x*ev.x + q[c].y*ev.y + q[c].z*ev.z + q[c].w*ev.w;
        }
        #pragma unroll
        for (int off = 16; off; off >>= 1)
            acc += __shfl_xor_sync(0xffffffffu, acc, off);
        if (lane == 0)
            sc[s] = (src_tokens[s*BSZ + b] != PAD_IDX) ? acc : NEGV;
    }
    __syncthreads();

    if (w == 0) {
        float v0 = sc[lane], v1 = sc[lane+32];
        float m = fmaxf(v0, v1);
        #pragma unroll
        for (int off = 16; off; off >>= 1)
            m = fmaxf(m, __shfl_xor_sync(0xffffffffu, m, off));
        float e0 = expf(v0 - m), e1 = expf(v1 - m);
        float ssum = e0 + e1;
        #pragma unroll
        for (int off = 16; off; off >>= 1)
            ssum += __shfl_xor_sync(0xffffffffu, ssum, off);
        sc[lane]    = e0/ssum;
        sc[lane+32] = e1/ssum;
    }
    __syncthreads();

    // ctx: each thread handles 4 consecutive h dims
    float4 a4 = make_float4(0.f, 0.f, 0.f, 0.f);
    for (int s = 0; s < SSZ; s++) {
        float at = sc[s];
        float4 ev = *(const float4*)(enc_out_t + ((size_t)s*BSZ + b)*HSZ + threadIdx.x*4);
        a4.x += at*ev.x; a4.y += at*ev.y; a4.z += at*ev.z; a4.w += at*ev.w;
    }
    *(float4*)(ctx_t + (size_t)b*HSZ + threadIdx.x*4) = a4;
}

// ---------------- GEMM: out[b][n] = act( X[b][:] . W[n][:] + bias[n] ) ----
// k split across lanes (float4), smem lane-reduction at the end.
// X is two concatenated [B][*] pieces (piece2 unused when K1 == KTOT).
template<int NVW, int NBW, int KTOT, int K1, bool DOTANH>
__global__ __launch_bounds__(256) void gemm_kt_kernel(
    const float* __restrict__ X1,        // [B][K1]
    const float* __restrict__ X2,        // [B][KTOT-K1]
    const float* __restrict__ W,         // [N][KTOT]
    const float* __restrict__ bias,      // [N]
    float* __restrict__ out, int ldo)    // out[b*ldo + n]
{
    constexpr int NOUT = NVW*NBW;
    int w = threadIdx.x >> 5, lane = threadIdx.x & 31;
    int vbase = blockIdx.y*(8*NVW) + w*NVW;   // v groups on .y (Wo rows shared across .x)
    int bbase = blockIdx.x*NBW;               // b groups on .x (adjacent in schedule)

    float acc[NOUT];
    #pragma unroll
    for (int i = 0; i < NOUT; i++) acc[i] = 0.f;

    constexpr int CH = KTOT/128;
    #pragma unroll 2
    for (int c = 0; c < CH; c++) {
        int k = c*128 + lane*4;
        float4 xv[NBW];
        #pragma unroll
        for (int jb = 0; jb < NBW; jb++) {
            const float* src = (k < K1)
                ? (X1 + (size_t)(bbase+jb)*K1 + k)
                : (X2 + (size_t)(bbase+jb)*(KTOT-K1) + (k - K1));
            xv[jb] = *(const float4*)src;
        }
        #pragma unroll
        for (int iv = 0; iv < NVW; iv++) {
            float4 wv = *(const float4*)(W + (size_t)(vbase+iv)*KTOT + k);
            #pragma unroll
            for (int jb = 0; jb < NBW; jb++) {
                acc[iv*NBW + jb] += wv.x*xv[jb].x + wv.y*xv[jb].y
                                  + wv.z*xv[jb].z + wv.w*xv[jb].w;
            }
        }
    }

    __shared__ float red[8][32][33];
    #pragma unroll
    for (int g = 0; g < NOUT; g += 32) {
        __syncwarp();
        #pragma unroll
        for (int i = 0; i < 32; i++)
            red[w][i][lane] = acc[g + i];
        __syncwarp();
        float s = 0.f;
        #pragma unroll
        for (int l = 0; l < 32; l++)
            s += red[w][lane][l];
        int oi = g + lane;
        int vi = oi / NBW, jb = oi % NBW;
        int v = vbase + vi;
        float val = s + bias[v];
        if (DOTANH) val = tanhf(val);
        out[(size_t)(bbase+jb)*ldo + v] = val;
    }
}

// ---------------- host ----------------
extern "C" void kernel_launch(void* const* d_in, const int* in_sizes, int n_in,
                              void* d_out, int out_size) {
    const int*   src_tokens = (const int*)  d_in[0];
    const int*   tgt_tokens = (const int*)  d_in[1];
    const float* enc_emb    = (const float*)d_in[2];
    const float* enc_Wih0   = (const float*)d_in[3];
    const float* enc_Whh0   = (const float*)d_in[4];
    const float* enc_bih0   = (const float*)d_in[5];
    const float* enc_bhh0   = (const float*)d_in[6];
    const float* enc_Wih1   = (const float*)d_in[7];
    const float* enc_Whh1   = (const float*)d_in[8];
    const float* enc_bih1   = (const float*)d_in[9];
    const float* enc_bhh1   = (const float*)d_in[10];
    const float* dec_emb    = (const float*)d_in[11];
    const float* dec_Wih0   = (const float*)d_in[12];
    const float* dec_Whh0   = (const float*)d_in[13];
    const float* dec_bih0   = (const float*)d_in[14];
    const float* dec_bhh0   = (const float*)d_in[15];
    const float* dec_Wih1   = (const float*)d_in[16];
    const float* dec_Whh1   = (const float*)d_in[17];
    const float* dec_bih1   = (const float*)d_in[18];
    const float* dec_bhh1   = (const float*)d_in[19];
    const float* Wc         = (const float*)d_in[20];
    const float* bc         = (const float*)d_in[21];
    const float* Wo         = (const float*)d_in[22];
    const float* bo         = (const float*)d_in[23];
    float* out = (float*)d_out;

    float *emb_src, *enc_out_t, *h0, *h1, *dh0, *dh1, *h1t, *ctx_t, *cc_t;
    cudaGetSymbolAddress((void**)&emb_src,   g_emb_src);
    cudaGetSymbolAddress((void**)&enc_out_t, g_enc_out_t);
    cudaGetSymbolAddress((void**)&h0,        g_h0);
    cudaGetSymbolAddress((void**)&h1,        g_h1);
    cudaGetSymbolAddress((void**)&dh0,       g_dh0);
    cudaGetSymbolAddress((void**)&dh1,       g_dh1);
    cudaGetSymbolAddress((void**)&h1t,       g_h1t);
    cudaGetSymbolAddress((void**)&ctx_t,     g_ctx_t);
    cudaGetSymbolAddress((void**)&cc_t,      g_cc_t);

    // out[0] = zeros, initial hidden = zeros
    zero_kernel<<<256, 256>>>(out, BSZ*VSZ);
    zero_kernel<<<64, 256>>>(h0, HB);
    zero_kernel<<<64, 256>>>(h1, HB);

    embed_kernel<<<(SSZ*ESZ*BSZ)/256, 256>>>(src_tokens, enc_emb, emb_src);

    // ---- encoder ----
    for (int t = 0; t < SSZ; t++) {
        int rp = t & 1, wp = rp ^ 1;
        gru_cell_kernel<<<128, 256>>>(
            emb_src + (size_t)t*ESZ*BSZ, ESZ, nullptr, nullptr,
            h0 + rp*HB, enc_Wih0, enc_Whh0, enc_bih0, enc_bhh0,
            h0 + wp*HB, nullptr);
        gru_cell_kernel<<<128, 256>>>(
            h0 + wp*HB, HSZ, nullptr, nullptr,
            h1 + rp*HB, enc_Wih1, enc_Whh1, enc_bih1, enc_bhh1,
            h1 + wp*HB, enc_out_t + (size_t)t*BSZ*HSZ);
    }
    // S=64 (even) -> final encoder hidden sits at parity 0 (h0+0, h1+0)

    // ---- decoder (teacher forced) ----
    for (int t = 0; t < TSZ-1; t++) {
        int wp = (t+1) & 1, rp = t & 1;
        const float* h0r = (t == 0) ? h0 : dh0 + rp*HB;
        const float* h1r = (t == 0) ? h1 : dh1 + rp*HB;

        gru_cell_kernel<<<128, 256>>>(
            nullptr, ESZ, tgt_tokens + t*BSZ, dec_emb,
            h0r, dec_Wih0, dec_Whh0, dec_bih0, dec_bhh0,
            dh0 + wp*HB, nullptr);
        gru_cell_kernel<<<128, 256>>>(
            dh0 + wp*HB, HSZ, nullptr, nullptr,
            h1r, dec_Wih1, dec_Whh1, dec_bih1, dec_bhh1,
            dh1 + wp*HB, h1t);

        attn_kernel<<<BSZ, 256>>>(h1t, enc_out_t, src_tokens, ctx_t);

        // cc = tanh([h1, ctx] @ Wc^T + bc), output transposed [B][H]
        gemm_kt_kernel<4, 8, 2048, 1024, true><<<dim3(4, 32), 256>>>(
            h1t, ctx_t, Wc, bc, cc_t, HSZ);

        // logits = cc @ Wo^T + bo  -> out[t+1]
        gemm_kt_kernel<8, 8, 1024, 1024, false><<<dim3(4, 500), 256>>>(
            cc_t, cc_t, Wo, bo, out + (size_t)(t+1)*BSZ*VSZ, VSZ);
    }
}

// round 2
// speedup vs baseline: 2.5999x; 2.5999x over previous
#include <cuda_runtime.h>
#include <math.h>

#define VSZ 32000
#define ESZ 512
#define HSZ 1024
#define SSZ 64
#define TSZ 64
#define BSZ 32
#define HB  (HSZ*BSZ)          // 32768
#define GB3 (3*HSZ*BSZ)        // 98304 gate elems per step
#define PAD_IDX 1
#define NEGV -100000.0f

// ---------------- device scratch ----------------
__device__ float g_emb_src[SSZ*ESZ*BSZ];        // [s][e][b]
__device__ float g_emb_dec[(TSZ-1)*ESZ*BSZ];    // [t][e][b]
__device__ float g_gx_enc[SSZ*3*HSZ*BSZ];       // [s][n][b]  (+bih0)
__device__ float g_gx_dec[(TSZ-1)*3*HSZ*BSZ];   // [t][n][b]  (+bih0)
__device__ float g_GX[GB3];                     // [n][b]
__device__ float g_GH[GB3];                     // [n][b]
__device__ float g_enc_out_t[SSZ*BSZ*HSZ];      // [s][b][h]
__device__ float g_h0[2*HB];                    // [h][b], double buffered
__device__ float g_h1[2*HB];
__device__ float g_dh0[2*HB];
__device__ float g_dh1[2*HB];
__device__ float g_h1t[BSZ*HSZ];                // [b][h]
__device__ float g_ctx_t[BSZ*HSZ];              // [b][h]
__device__ float g_cc_all[TSZ*BSZ*HSZ];         // [t][b][h]  (row 63 stays 0)

// ---------------- utility ----------------
__global__ void zero_kernel(float* p, int n) {
    for (int i = blockIdx.x*blockDim.x + threadIdx.x; i < n; i += gridDim.x*blockDim.x)
        p[i] = 0.f;
}

// out[s][e][b] = emb[tok[s][b]][e]   (E=512 fixed)
__global__ void embed_kernel(const int* __restrict__ tok,
                             const float* __restrict__ emb,
                             float* __restrict__ out) {
    int idx = blockIdx.x*256 + threadIdx.x;
    int b = idx & 31;
    int e = (idx >> 5) & (ESZ-1);
    int s = idx >> 14;
    out[idx] = emb[(size_t)tok[s*BSZ + b]*ESZ + e];
}

// ---------------- gate GEMM: Out[n][b] = bias[n] + sum_k W[n][k]*X[k][b] ----
// Optionally two (X,W,bias,Out) pairs fused (shared schedule, separate tiles).
// Warp-per-n, 8 warps/block, grid.x = 3H/8 = 384 -> ~21 warps/SM.
template<bool HASA, int K>
__global__ __launch_bounds__(256) void step_gemm(
    const float* __restrict__ XA, const float* __restrict__ WA,
    const float* __restrict__ bA, float* __restrict__ OA,
    const float* __restrict__ XB, const float* __restrict__ WB,
    const float* __restrict__ bB, float* __restrict__ OB,
    int xstride, int ostride)
{
    __shared__ float SA[128*36];
    __shared__ float SB[128*36];
    int tid = threadIdx.x;
    int w = tid >> 5, lane = tid & 31;
    int n = blockIdx.x*8 + w;
    XB += (size_t)blockIdx.y * xstride;
    OB += (size_t)blockIdx.y * ostride;

    float a0=0.f,a1=0.f,a2=0.f,a3=0.f;
    float b0=0.f,b1=0.f,b2=0.f,b3=0.f;

    int bg  = tid & 7;          // b-group (float4)
    int kkb = tid >> 3;         // 0..31

    #pragma unroll
    for (int k0 = 0; k0 < K; k0 += 128) {
        __syncthreads();
        #pragma unroll
        for (int i2 = 0; i2 < 4; i2++) {
            int kk = kkb + 32*i2;
            *(float4*)(SB + kk*36 + bg*4) =
                *(const float4*)(XB + (size_t)(k0+kk)*BSZ + bg*4);
            if (HASA)
                *(float4*)(SA + kk*36 + bg*4) =
                    *(const float4*)(XA + (size_t)(k0+kk)*BSZ + bg*4);
        }
        __syncthreads();

        const float4* wb = (const float4*)(WB + (size_t)n*K + k0);
        #pragma unroll
        for (int q = 0; q < 32; q++) {
            float4 wv = wb[q];
            b0 += wv.x * SB[(q*4+0)*36 + lane];
            b1 += wv.y * SB[(q*4+1)*36 + lane];
            b2 += wv.z * SB[(q*4+2)*36 + lane];
            b3 += wv.w * SB[(q*4+3)*36 + lane];
        }
        if (HASA) {
            const float4* wa = (const float4*)(WA + (size_t)n*K + k0);
            #pragma unroll
            for (int q = 0; q < 32; q++) {
                float4 wv = wa[q];
                a0 += wv.x * SA[(q*4+0)*36 + lane];
                a1 += wv.y * SA[(q*4+1)*36 + lane];
                a2 += wv.z * SA[(q*4+2)*36 + lane];
                a3 += wv.w * SA[(q*4+3)*36 + lane];
            }
        }
    }
    OB[n*BSZ + lane] = b0+b1+b2+b3 + bB[n];
    if (HASA)
        OA[n*BSZ + lane] = a0+a1+a2+a3 + bA[n];
}

// ---------------- GRU elementwise combine ----------------
// GX includes bih, GH includes bhh.
__global__ __launch_bounds__(256) void gru_combine(
    const float* __restrict__ GX, const float* __restrict__ GH,
    const float* __restrict__ h_old,
    float* __restrict__ h_new,
    float* __restrict__ h1t,        // [b][h] or null
    float* __restrict__ enc_out)    // pre-offset [b][h] or null
{
    int idx = blockIdx.x*256 + threadIdx.x;   // 32768 total
    int j = idx >> 5, b = idx & 31;
    float r  = 1.f/(1.f + expf(-(GX[idx]      + GH[idx])));
    float z  = 1.f/(1.f + expf(-(GX[idx+HB]   + GH[idx+HB])));
    float nn = tanhf(GX[idx+2*HB] + r*GH[idx+2*HB]);
    float h  = (1.f - z)*nn + z*h_old[idx];
    h_new[idx] = h;
    if (h1t)     h1t[(size_t)b*HSZ + j] = h;
    if (enc_out) enc_out[(size_t)b*HSZ + j] = h;
}

// ---------------- attention (one block per batch element) ----------------
__global__ __launch_bounds__(256) void attn_kernel(
    const float* __restrict__ h1t,        // [B][H]
    const float* __restrict__ enc_out_t,  // [S][B][H]
    const int*   __restrict__ src_tokens, // [S][B]
    float* __restrict__ ctx_t)            // [B][H]
{
    int b = blockIdx.x;
    int w = threadIdx.x >> 5, lane = threadIdx.x & 31;
    __shared__ float sc[64];

    float4 q[8];
    #pragma unroll
    for (int c = 0; c < 8; c++)
        q[c] = *(const float4*)(h1t + (size_t)b*HSZ + c*128 + lane*4);

    #pragma unroll
    for (int i = 0; i < 8; i++) {
        int s = w*8 + i;
        const float* e = enc_out_t + ((size_t)s*BSZ + b)*HSZ;
        float acc = 0.f;
        #pragma unroll
        for (int c = 0; c < 8; c++) {
            float4 ev = *(const float4*)(e + c*128 + lane*4);
            acc += q[c].x*ev.x + q[c].y*ev.y + q[c].z*ev.z + q[c].w*ev.w;
        }
        #pragma unroll
        for (int off = 16; off; off >>= 1)
            acc += __shfl_xor_sync(0xffffffffu, acc, off);
        if (lane == 0)
            sc[s] = (src_tokens[s*BSZ + b] != PAD_IDX) ? acc : NEGV;
    }
    __syncthreads();

    if (w == 0) {
        float v0 = sc[lane], v1 = sc[lane+32];
        float m = fmaxf(v0, v1);
        #pragma unroll
        for (int off = 16; off; off >>= 1)
            m = fmaxf(m, __shfl_xor_sync(0xffffffffu, m, off));
        float e0 = expf(v0 - m), e1 = expf(v1 - m);
        float ssum = e0 + e1;
        #pragma unroll
        for (int off = 16; off; off >>= 1)
            ssum += __shfl_xor_sync(0xffffffffu, ssum, off);
        sc[lane]    = e0/ssum;
        sc[lane+32] = e1/ssum;
    }
    __syncthreads();

    float4 a4 = make_float4(0.f, 0.f, 0.f, 0.f);
    for (int s = 0; s < SSZ; s++) {
        float at = sc[s];
        float4 ev = *(const float4*)(enc_out_t + ((size_t)s*BSZ + b)*HSZ + threadIdx.x*4);
        a4.x += at*ev.x; a4.y += at*ev.y; a4.z += at*ev.z; a4.w += at*ev.w;
    }
    *(float4*)(ctx_t + (size_t)b*HSZ + threadIdx.x*4) = a4;
}

// ---------------- cc GEMM (k-split across lanes) ----------------
template<int NVW, int NBW, int KTOT, int K1, bool DOTANH>
__global__ __launch_bounds__(256) void gemm_kt_kernel(
    const float* __restrict__ X1, const float* __restrict__ X2,
    const float* __restrict__ W,  const float* __restrict__ bias,
    float* __restrict__ out, int ldo)
{
    constexpr int NOUT = NVW*NBW;
    int w = threadIdx.x >> 5, lane = threadIdx.x & 31;
    int vbase = blockIdx.y*(8*NVW) + w*NVW;
    int bbase = blockIdx.x*NBW;

    float acc[NOUT];
    #pragma unroll
    for (int i = 0; i < NOUT; i++) acc[i] = 0.f;

    constexpr int CH = KTOT/128;
    #pragma unroll 2
    for (int c = 0; c < CH; c++) {
        int k = c*128 + lane*4;
        float4 xv[NBW];
        #pragma unroll
        for (int jb = 0; jb < NBW; jb++) {
            const float* src = (k < K1)
                ? (X1 + (size_t)(bbase+jb)*K1 + k)
                : (X2 + (size_t)(bbase+jb)*(KTOT-K1) + (k - K1));
            xv[jb] = *(const float4*)src;
        }
        #pragma unroll
        for (int iv = 0; iv < NVW; iv++) {
            float4 wv = *(const float4*)(W + (size_t)(vbase+iv)*KTOT + k);
            #pragma unroll
            for (int jb = 0; jb < NBW; jb++) {
                acc[iv*NBW + jb] += wv.x*xv[jb].x + wv.y*xv[jb].y
                                  + wv.z*xv[jb].z + wv.w*xv[jb].w;
            }
        }
    }

    __shared__ float red[8][32][33];
    #pragma unroll
    for (int g = 0; g < NOUT; g += 32) {
        __syncwarp();
        #pragma unroll
        for (int i = 0; i < 32; i++)
            red[w][i][lane] = acc[g + i];
        __syncwarp();
        float s = 0.f;
        #pragma unroll
        for (int l = 0; l < 32; l++)
            s += red[w][lane][l];
        int oi = g + lane;
        int vi = oi / NBW, jb = oi % NBW;
        int v = vbase + vi;
        float val = s + bias[v];
        if (DOTANH) val = tanhf(val);
        out[(size_t)(bbase+jb)*ldo + v] = val;
    }
}

// ---------------- batched logits GEMM ----------------
// C[m][v] = A[m][:]·W[v][:] + bo[v],  A=[2048][1024] (cc_all), W=[32000][1024]
// 64x64 block tile, 256 threads, 4x4 per-thread tile, double-buffered smem.
__global__ __launch_bounds__(256) void logits_gemm(
    const float* __restrict__ A,
    const float* __restrict__ W,
    const float* __restrict__ bo,
    float* __restrict__ out)
{
    __shared__ float As[2][16][64];
    __shared__ float Ws[2][16][64];
    int tid = threadIdx.x;
    int mb = blockIdx.y*64, vb = blockIdx.x*64;

    int lr = tid >> 2;            // 0..63
    int lc = (tid & 3) * 4;       // 0,4,8,12
    const float* Ag = A + (size_t)(mb+lr)*HSZ + lc;
    const float* Wg = W + (size_t)(vb+lr)*HSZ + lc;

    int tm = (tid & 15) * 4;
    int tv = (tid >> 4) * 4;

    float acc[16];
    #pragma unroll
    for (int i = 0; i < 16; i++) acc[i] = 0.f;

    float4 pa = *(const float4*)Ag;
    float4 pw = *(const float4*)Wg;

    for (int c = 0; c < 64; c++) {
        int buf = c & 1;
        As[buf][lc+0][lr] = pa.x; As[buf][lc+1][lr] = pa.y;
        As[buf][lc+2][lr] = pa.z; As[buf][lc+3][lr] = pa.w;
        Ws[buf][lc+0][lr] = pw.x; Ws[buf][lc+1][lr] = pw.y;
        Ws[buf][lc+2][lr] = pw.z; Ws[buf][lc+3][lr] = pw.w;
        __syncthreads();
        if (c < 63) {
            pa = *(const float4*)(Ag + (c+1)*16);
            pw = *(const float4*)(Wg + (c+1)*16);
        }
        #pragma unroll
        for (int kk = 0; kk < 16; kk++) {
            float4 av = *(const float4*)&As[buf][kk][tm];
            float4 wv = *(const float4*)&Ws[buf][kk][tv];
            acc[0]  += av.x*wv.x; acc[1]  += av.x*wv.y; acc[2]  += av.x*wv.z; acc[3]  += av.x*wv.w;
            acc[4]  += av.y*wv.x; acc[5]  += av.y*wv.y; acc[6]  += av.y*wv.z; acc[7]  += av.y*wv.w;
            acc[8]  += av.z*wv.x; acc[9]  += av.z*wv.y; acc[10] += av.z*wv.z; acc[11] += av.z*wv.w;
            acc[12] += av.w*wv.x; acc[13] += av.w*wv.y; acc[14] += av.w*wv.z; acc[15] += av.w*wv.w;
        }
    }

    #pragma unroll
    for (int i = 0; i < 4; i++) {
        int m = mb + tm + i;
        if (m < (TSZ-1)*BSZ) {
            #pragma unroll
            for (int j = 0; j < 4; j++) {
                int v = vb + tv + j;
                out[(size_t)(m + BSZ)*VSZ + v] = acc[i*4+j] + bo[v];
            }
        }
    }
}

// ---------------- host ----------------
extern "C" void kernel_launch(void* const* d_in, const int* in_sizes, int n_in,
                              void* d_out, int out_size) {
    const int*   src_tokens = (const int*)  d_in[0];
    const int*   tgt_tokens = (const int*)  d_in[1];
    const float* enc_emb    = (const float*)d_in[2];
    const float* enc_Wih0   = (const float*)d_in[3];
    const float* enc_Whh0   = (const float*)d_in[4];
    const float* enc_bih0   = (const float*)d_in[5];
    const float* enc_bhh0   = (const float*)d_in[6];
    const float* enc_Wih1   = (const float*)d_in[7];
    const float* enc_Whh1   = (const float*)d_in[8];
    const float* enc_bih1   = (const float*)d_in[9];
    const float* enc_bhh1   = (const float*)d_in[10];
    const float* dec_emb    = (const float*)d_in[11];
    const float* dec_Wih0   = (const float*)d_in[12];
    const float* dec_Whh0   = (const float*)d_in[13];
    const float* dec_bih0   = (const float*)d_in[14];
    const float* dec_bhh0   = (const float*)d_in[15];
    const float* dec_Wih1   = (const float*)d_in[16];
    const float* dec_Whh1   = (const float*)d_in[17];
    const float* dec_bih1   = (const float*)d_in[18];
    const float* dec_bhh1   = (const float*)d_in[19];
    const float* Wc         = (const float*)d_in[20];
    const float* bc         = (const float*)d_in[21];
    const float* Wo         = (const float*)d_in[22];
    const float* bo         = (const float*)d_in[23];
    float* out = (float*)d_out;

    float *emb_src, *emb_dec, *gx_enc, *gx_dec, *GX, *GH;
    float *enc_out_t, *h0, *h1, *dh0, *dh1, *h1t, *ctx_t, *cc_all;
    cudaGetSymbolAddress((void**)&emb_src,   g_emb_src);
    cudaGetSymbolAddress((void**)&emb_dec,   g_emb_dec);
    cudaGetSymbolAddress((void**)&gx_enc,    g_gx_enc);
    cudaGetSymbolAddress((void**)&gx_dec,    g_gx_dec);
    cudaGetSymbolAddress((void**)&GX,        g_GX);
    cudaGetSymbolAddress((void**)&GH,        g_GH);
    cudaGetSymbolAddress((void**)&enc_out_t, g_enc_out_t);
    cudaGetSymbolAddress((void**)&h0,        g_h0);
    cudaGetSymbolAddress((void**)&h1,        g_h1);
    cudaGetSymbolAddress((void**)&dh0,       g_dh0);
    cudaGetSymbolAddress((void**)&dh1,       g_dh1);
    cudaGetSymbolAddress((void**)&h1t,       g_h1t);
    cudaGetSymbolAddress((void**)&ctx_t,     g_ctx_t);
    cudaGetSymbolAddress((void**)&cc_all,    g_cc_all);

    // out row 0 = zeros, initial hiddens = zeros
    zero_kernel<<<1024, 256>>>(out, BSZ*VSZ);
    zero_kernel<<<64, 256>>>(h0, HB);
    zero_kernel<<<64, 256>>>(h1, HB);

    // embeddings
    embed_kernel<<<(SSZ*ESZ*BSZ)/256, 256>>>(src_tokens, enc_emb, emb_src);
    embed_kernel<<<((TSZ-1)*ESZ*BSZ)/256, 256>>>(tgt_tokens, dec_emb, emb_dec);

    // hoisted input projections (layer 0), bih0 folded in
    step_gemm<false, ESZ><<<dim3(384, SSZ), 256>>>(
        nullptr, nullptr, nullptr, nullptr,
        emb_src, enc_Wih0, enc_bih0, gx_enc, ESZ*BSZ, 3*HSZ*BSZ);
    step_gemm<false, ESZ><<<dim3(384, TSZ-1), 256>>>(
        nullptr, nullptr, nullptr, nullptr,
        emb_dec, dec_Wih0, dec_bih0, gx_dec, ESZ*BSZ, 3*HSZ*BSZ);

    // ---- encoder ----
    for (int t = 0; t < SSZ; t++) {
        int rp = t & 1, wp = rp ^ 1;
        step_gemm<false, HSZ><<<384, 256>>>(
            nullptr, nullptr, nullptr, nullptr,
            h0 + rp*HB, enc_Whh0, enc_bhh0, GH, 0, 0);
        gru_combine<<<128, 256>>>(gx_enc + (size_t)t*3*HSZ*BSZ, GH,
                                  h0 + rp*HB, h0 + wp*HB, nullptr, nullptr);
        step_gemm<true, HSZ><<<384, 256>>>(
            h0 + wp*HB, enc_Wih1, enc_bih1, GX,
            h1 + rp*HB, enc_Whh1, enc_bhh1, GH, 0, 0);
        gru_combine<<<128, 256>>>(GX, GH, h1 + rp*HB, h1 + wp*HB,
                                  nullptr, enc_out_t + (size_t)t*BSZ*HSZ);
    }
    // S even -> final encoder hidden at parity 0

    // ---- decoder ----
    for (int t = 0; t < TSZ-1; t++) {
        int wp = (t+1) & 1, rp = t & 1;
        const float* h0r = (t == 0) ? h0 : dh0 + rp*HB;
        const float* h1r = (t == 0) ? h1 : dh1 + rp*HB;

        step_gemm<false, HSZ><<<384, 256>>>(
            nullptr, nullptr, nullptr, nullptr,
            h0r, dec_Whh0, dec_bhh0, GH, 0, 0);
        gru_combine<<<128, 256>>>(gx_dec + (size_t)t*3*HSZ*BSZ, GH,
                                  h0r, dh0 + wp*HB, nullptr, nullptr);
        step_gemm<true, HSZ><<<384, 256>>>(
            dh0 + wp*HB, dec_Wih1, dec_bih1, GX,
            h1r, dec_Whh1, dec_bhh1, GH, 0, 0);
        gru_combine<<<128, 256>>>(GX, GH, h1r, dh1 + wp*HB, h1t, nullptr);

        attn_kernel<<<BSZ, 256>>>(h1t, enc_out_t, src_tokens, ctx_t);

        gemm_kt_kernel<4, 8, 2*HSZ, HSZ, true><<<dim3(4, 32), 256>>>(
            h1t, ctx_t, Wc, bc, cc_all + (size_t)t*BSZ*HSZ, HSZ);
    }

    // ---- one batched logits GEMM over all timesteps ----
    logits_gemm<<<dim3(VSZ/64, (TSZ*BSZ)/64), 256>>>(cc_all, Wo, bo, out);
}

// round 5
// speedup vs baseline: 4.2717x; 1.6431x over previous
#include <cuda_runtime.h>
#include <math.h>
#include <stdint.h>

#define VSZ 32000
#define ESZ 512
#define HSZ 1024
#define SSZ 64
#define TSZ 64
#define BSZ 32
#define HB  (HSZ*BSZ)          // 32768
#define PAD_IDX 1
#define NEGV -100000.0f

// ---------------- device scratch ----------------
__device__ float g_emb_src[SSZ*BSZ*ESZ];        // [m=(s,b)][e]
__device__ float g_emb_dec[TSZ*BSZ*ESZ];        // [m=(t,b)][e]
__device__ float g_gx_enc[SSZ*3*HSZ*BSZ];       // [s][n][b]  (+bih0)
__device__ float g_gx_dec[TSZ*3*HSZ*BSZ];       // [t][n][b]  (+bih0)
__device__ float g_enc_out_t[SSZ*BSZ*HSZ];      // [s][b][h]
__device__ float g_h0[2*HB];                    // [h][b], double buffered
__device__ float g_h1[2*HB];
__device__ float g_dh0[2*HB];
__device__ float g_dh1[2*HB];
__device__ float g_h1t[BSZ*HSZ];                // [b][h]
__device__ float g_ctx_t[BSZ*HSZ];              // [b][h]
__device__ float g_cc_all[TSZ*BSZ*HSZ];         // [m=(t,b)][h], tf32-rounded
__device__ float g_wo_tf[VSZ*HSZ];              // Wo, tf32-rounded

// ---------------- helpers ----------------
__device__ __forceinline__ uint32_t f2tf32(float f) {
    uint32_t u;
    asm("cvt.rna.tf32.f32 %0, %1;" : "=r"(u) : "f"(f));
    return u;
}
__device__ __forceinline__ void cp16(uint32_t s, const void* g) {
    asm volatile("cp.async.cg.shared.global [%0], [%1], 16;" :: "r"(s), "l"(g));
}
#define CP_COMMIT() asm volatile("cp.async.commit_group;" ::: "memory")
#define CP_WAIT(N)  asm volatile("cp.async.wait_group %0;" :: "n"(N) : "memory")

__device__ __forceinline__ void mma_tf32(float* c, const uint32_t* a, const uint32_t* b) {
    asm volatile(
        "mma.sync.aligned.m16n8k8.row.col.f32.tf32.tf32.f32 "
        "{%0,%1,%2,%3},{%4,%5,%6,%7},{%8,%9},{%0,%1,%2,%3};"
        : "+f"(c[0]), "+f"(c[1]), "+f"(c[2]), "+f"(c[3])
        : "r"(a[0]), "r"(a[1]), "r"(a[2]), "r"(a[3]), "r"(b[0]), "r"(b[1]));
}

// ---------------- utility kernels ----------------
__global__ void zero_kernel(float* p, int n) {
    for (int i = blockIdx.x*blockDim.x + threadIdx.x; i < n; i += gridDim.x*blockDim.x)
        p[i] = 0.f;
}
__global__ void zero_h2_kernel(float* a, float* b) {
    int i = blockIdx.x*256 + threadIdx.x;
    if (i < HB) a[i] = 0.f; else b[i - HB] = 0.f;
}
__global__ void cvt_tf32_kernel(const float* __restrict__ in, float* __restrict__ out) {
    int i = blockIdx.x*256 + threadIdx.x;     // n/4 threads
    float4 v = ((const float4*)in)[i];
    uint4 u = make_uint4(f2tf32(v.x), f2tf32(v.y), f2tf32(v.z), f2tf32(v.w));
    ((uint4*)out)[i] = u;
}

// out[m][e] = emb[tok[m]][e]
__global__ void embed_kernel(const int* __restrict__ tok,
                             const float* __restrict__ emb,
                             float* __restrict__ out, int rows) {
    int idx = blockIdx.x*256 + threadIdx.x;
    if (idx >= rows*ESZ) return;
    int e = idx & (ESZ-1);
    int m = idx >> 9;
    out[idx] = emb[(size_t)tok[m]*ESZ + e];
}

// ---------------- input projection: gx[t][n][b] = W[n][:]·X[m][:] + bih[n] ----
__global__ __launch_bounds__(256) void proj_gemm(
    const float* __restrict__ X,   // [M][512]
    const float* __restrict__ W,   // [3072][512]
    const float* __restrict__ bih,
    float* __restrict__ gx)        // [t][n][b]
{
    __shared__ float Xs[2][16][64];
    __shared__ float Ws[2][16][64];
    int tid = threadIdx.x;
    int mb = blockIdx.x*64, nb = blockIdx.y*64;
    int lr = tid >> 2, lc = (tid & 3) * 4;
    const float* Xg = X + (size_t)(mb+lr)*ESZ + lc;
    const float* Wg = W + (size_t)(nb+lr)*ESZ + lc;
    int tm = (tid & 15) * 4, tn = (tid >> 4) * 4;

    float acc[16];
    #pragma unroll
    for (int i = 0; i < 16; i++) acc[i] = 0.f;

    float4 px = *(const float4*)Xg;
    float4 pw = *(const float4*)Wg;
    for (int c = 0; c < 32; c++) {
        int buf = c & 1;
        Xs[buf][lc+0][lr]=px.x; Xs[buf][lc+1][lr]=px.y; Xs[buf][lc+2][lr]=px.z; Xs[buf][lc+3][lr]=px.w;
        Ws[buf][lc+0][lr]=pw.x; Ws[buf][lc+1][lr]=pw.y; Ws[buf][lc+2][lr]=pw.z; Ws[buf][lc+3][lr]=pw.w;
        __syncthreads();
        if (c < 31) {
            px = *(const float4*)(Xg + (c+1)*16);
            pw = *(const float4*)(Wg + (c+1)*16);
        }
        #pragma unroll
        for (int kk = 0; kk < 16; kk++) {
            float4 av = *(const float4*)&Xs[buf][kk][tm];
            float4 wv = *(const float4*)&Ws[buf][kk][tn];
            acc[0]+=av.x*wv.x; acc[1]+=av.x*wv.y; acc[2]+=av.x*wv.z; acc[3]+=av.x*wv.w;
            acc[4]+=av.y*wv.x; acc[5]+=av.y*wv.y; acc[6]+=av.y*wv.z; acc[7]+=av.y*wv.w;
            acc[8]+=av.z*wv.x; acc[9]+=av.z*wv.y; acc[10]+=av.z*wv.z; acc[11]+=av.z*wv.w;
            acc[12]+=av.w*wv.x; acc[13]+=av.w*wv.y; acc[14]+=av.w*wv.z; acc[15]+=av.w*wv.w;
        }
        __syncthreads();
    }
    #pragma unroll
    for (int i = 0; i < 4; i++) {
        int m = mb + tm + i;
        int t = m >> 5, b = m & 31;
        #pragma unroll
        for (int j = 0; j < 4; j++) {
            int n = nb + tn + j;
            gx[(size_t)t*3*HSZ*BSZ + (size_t)n*BSZ + b] = acc[i*4+j] + bih[n];
        }
    }
}

// ---------------- fused GRU layer-0 step ----------------
__global__ __launch_bounds__(256) void gru_l0(
    const float* __restrict__ gx,     // [3H][B]
    const float* __restrict__ h_old,  // [H][B]
    const float* __restrict__ Whh,    // [3H][H]
    const float* __restrict__ bhh,
    float* __restrict__ h_new)
{
    __shared__ float X[2][128][36];
    __shared__ float R[4][3][32];
    int tid = threadIdx.x, w = tid >> 5, lane = tid & 31;
    int p = w & 3, hf = w >> 2;
    int j = blockIdx.x*4 + p;
    const float* wr = Whh + (size_t)j*HSZ          + hf*512;
    const float* wz = Whh + (size_t)(HSZ+j)*HSZ    + hf*512;
    const float* wn = Whh + (size_t)(2*HSZ+j)*HSZ  + hf*512;
    float ar=0.f, az=0.f, an=0.f;

    for (int i = 0; i < 4; i++) {
        __syncthreads();
        #pragma unroll
        for (int it = 0; it < 8; it++) {
            int r = (tid >> 3) + it*32;            // 0..255
            int h = r >> 7, kk = r & 127;
            int gk = h*512 + i*128 + kk;
            *(float4*)&X[h][kk][(tid & 7)*4] =
                *(const float4*)(h_old + (size_t)gk*BSZ + (tid & 7)*4);
        }
        __syncthreads();
        #pragma unroll
        for (int q = 0; q < 32; q++) {
            float4 r4 = *(const float4*)(wr + i*128 + q*4);
            float4 z4 = *(const float4*)(wz + i*128 + q*4);
            float4 n4 = *(const float4*)(wn + i*128 + q*4);
            float x0 = X[hf][q*4+0][lane], x1 = X[hf][q*4+1][lane];
            float x2 = X[hf][q*4+2][lane], x3 = X[hf][q*4+3][lane];
            ar += r4.x*x0 + r4.y*x1 + r4.z*x2 + r4.w*x3;
            az += z4.x*x0 + z4.y*x1 + z4.z*x2 + z4.w*x3;
            an += n4.x*x0 + n4.y*x1 + n4.z*x2 + n4.w*x3;
        }
    }
    if (hf == 1) { R[p][0][lane]=ar; R[p][1][lane]=az; R[p][2][lane]=an; }
    __syncthreads();
    if (hf == 0) {
        float ghr = ar + R[p][0][lane] + bhh[j];
        float ghz = az + R[p][1][lane] + bhh[HSZ+j];
        float ghn = an + R[p][2][lane] + bhh[2*HSZ+j];
        float gr = gx[(size_t)j*BSZ + lane]         + ghr;
        float gz = gx[(size_t)(HSZ+j)*BSZ + lane]   + ghz;
        float r = 1.f/(1.f + expf(-gr));
        float z = 1.f/(1.f + expf(-gz));
        float n = tanhf(gx[(size_t)(2*HSZ+j)*BSZ + lane] + r*ghn);
        float hp = h_old[(size_t)j*BSZ + lane];
        h_new[(size_t)j*BSZ + lane] = (1.f - z)*n + z*hp;
    }
}

// ---------------- fused GRU layer-1 step ----------------
// dynamic smem: X[2 src][2 half][64][36]
#define L1_SMEM (2*2*64*36*4)
__global__ __launch_bounds__(256) void gru_l1(
    const float* __restrict__ x0,     // [H][B]
    const float* __restrict__ h1o,    // [H][B]
    const float* __restrict__ Wih,    // [3H][H]
    const float* __restrict__ bih,
    const float* __restrict__ Whh,    // [3H][H]
    const float* __restrict__ bhh,
    float* __restrict__ h_new,        // [H][B]
    float* __restrict__ h1t,          // [B][H] or null
    float* __restrict__ enc_out)      // [B][H] (pre-offset) or null
{
    extern __shared__ float Xd[];
    #define XL(s,h,kk,b) Xd[(((s)*2+(h))*64+(kk))*36+(b)]
    __shared__ float R[4][6][32];
    int tid = threadIdx.x, w = tid >> 5, lane = tid & 31;
    int p = w & 3, hf = w >> 2;
    int j = blockIdx.x*4 + p;
    const float* wxr = Wih + (size_t)j*HSZ          + hf*512;
    const float* wxz = Wih + (size_t)(HSZ+j)*HSZ    + hf*512;
    const float* wxn = Wih + (size_t)(2*HSZ+j)*HSZ  + hf*512;
    const float* whr = Whh + (size_t)j*HSZ          + hf*512;
    const float* whz = Whh + (size_t)(HSZ+j)*HSZ    + hf*512;
    const float* whn = Whh + (size_t)(2*HSZ+j)*HSZ  + hf*512;
    float xr=0.f,xz=0.f,xn=0.f, hr=0.f,hz=0.f,hn=0.f;

    for (int i = 0; i < 8; i++) {
        __syncthreads();
        #pragma unroll
        for (int it = 0; it < 8; it++) {
            int r = (tid >> 3) + it*32;           // 0..255
            int src = r >> 7, rr = r & 127;
            int h = rr >> 6, kk = rr & 63;
            int gk = h*512 + i*64 + kk;
            const float* s = src ? h1o : x0;
            *(float4*)&XL(src, h, kk, (tid & 7)*4) =
                *(const float4*)(s + (size_t)gk*BSZ + (tid & 7)*4);
        }
        __syncthreads();
        #pragma unroll
        for (int q = 0; q < 16; q++) {
            float4 a4 = *(const float4*)(wxr + i*64 + q*4);
            float4 b4 = *(const float4*)(wxz + i*64 + q*4);
            float4 c4 = *(const float4*)(wxn + i*64 + q*4);
            float4 d4 = *(const float4*)(whr + i*64 + q*4);
            float4 e4 = *(const float4*)(whz + i*64 + q*4);
            float4 f4 = *(const float4*)(whn + i*64 + q*4);
            float u0 = XL(0,hf,q*4+0,lane), u1 = XL(0,hf,q*4+1,lane);
            float u2 = XL(0,hf,q*4+2,lane), u3 = XL(0,hf,q*4+3,lane);
            float v0 = XL(1,hf,q*4+0,lane), v1 = XL(1,hf,q*4+1,lane);
            float v2 = XL(1,hf,q*4+2,lane), v3 = XL(1,hf,q*4+3,lane);
            xr += a4.x*u0 + a4.y*u1 + a4.z*u2 + a4.w*u3;
            xz += b4.x*u0 + b4.y*u1 + b4.z*u2 + b4.w*u3;
            xn += c4.x*u0 + c4.y*u1 + c4.z*u2 + c4.w*u3;
            hr += d4.x*v0 + d4.y*v1 + d4.z*v2 + d4.w*v3;
            hz += e4.x*v0 + e4.y*v1 + e4.z*v2 + e4.w*v3;
            hn += f4.x*v0 + f4.y*v1 + f4.z*v2 + f4.w*v3;
        }
    }
    if (hf == 1) {
        R[p][0][lane]=xr; R[p][1][lane]=xz; R[p][2][lane]=xn;
        R[p][3][lane]=hr; R[p][4][lane]=hz; R[p][5][lane]=hn;
    }
    __syncthreads();
    if (hf == 0) {
        float txr = xr + R[p][0][lane] + bih[j];
        float txz = xz + R[p][1][lane] + bih[HSZ+j];
        float txn = xn + R[p][2][lane] + bih[2*HSZ+j];
        float thr = hr + R[p][3][lane] + bhh[j];
        float thz = hz + R[p][4][lane] + bhh[HSZ+j];
        float thn = hn + R[p][5][lane] + bhh[2*HSZ+j];
        float r = 1.f/(1.f + expf(-(txr + thr)));
        float z = 1.f/(1.f + expf(-(txz + thz)));
        float n = tanhf(txn + r*thn);
        float hp = h1o[(size_t)j*BSZ + lane];
        float h = (1.f - z)*n + z*hp;
        h_new[(size_t)j*BSZ + lane] = h;
        if (h1t)     h1t[(size_t)lane*HSZ + j] = h;
        if (enc_out) enc_out[(size_t)lane*HSZ + j] = h;
    }
}

// ---------------- attention (one block per batch element) ----------------
__global__ __launch_bounds__(256) void attn_kernel(
    const float* __restrict__ h1t,
    const float* __restrict__ enc_out_t,
    const int*   __restrict__ src_tokens,
    float* __restrict__ ctx_t)
{
    int b = blockIdx.x;
    int w = threadIdx.x >> 5, lane = threadIdx.x & 31;
    __shared__ float sc[64];

    float4 q[8];
    #pragma unroll
    for (int c = 0; c < 8; c++)
        q[c] = *(const float4*)(h1t + (size_t)b*HSZ + c*128 + lane*4);

    #pragma unroll
    for (int i = 0; i < 8; i++) {
        int s = w*8 + i;
        const float* e = enc_out_t + ((size_t)s*BSZ + b)*HSZ;
        float acc = 0.f;
        #pragma unroll
        for (int c = 0; c < 8; c++) {
            float4 ev = *(const float4*)(e + c*128 + lane*4);
            acc += q[c].x*ev.x + q[c].y*ev.y + q[c].z*ev.z + q[c].w*ev.w;
        }
        #pragma unroll
        for (int off = 16; off; off >>= 1)
            acc += __shfl_xor_sync(0xffffffffu, acc, off);
        if (lane == 0)
            sc[s] = (src_tokens[s*BSZ + b] != PAD_IDX) ? acc : NEGV;
    }
    __syncthreads();

    if (w == 0) {
        float v0 = sc[lane], v1 = sc[lane+32];
        float m = fmaxf(v0, v1);
        #pragma unroll
        for (int off = 16; off; off >>= 1)
            m = fmaxf(m, __shfl_xor_sync(0xffffffffu, m, off));
        float e0 = expf(v0 - m), e1 = expf(v1 - m);
        float ssum = e0 + e1;
        #pragma unroll
        for (int off = 16; off; off >>= 1)
            ssum += __shfl_xor_sync(0xffffffffu, ssum, off);
        sc[lane]    = e0/ssum;
        sc[lane+32] = e1/ssum;
    }
    __syncthreads();

    float4 a4 = make_float4(0.f, 0.f, 0.f, 0.f);
    for (int s = 0; s < SSZ; s++) {
        float at = sc[s];
        float4 ev = *(const float4*)(enc_out_t + ((size_t)s*BSZ + b)*HSZ + threadIdx.x*4);
        a4.x += at*ev.x; a4.y += at*ev.y; a4.z += at*ev.z; a4.w += at*ev.w;
    }
    *(float4*)(ctx_t + (size_t)b*HSZ + threadIdx.x*4) = a4;
}

// ---------------- cc GEMM (k-split across lanes), stores tf32-rounded ------
template<int NVW, int NBW, int KTOT, int K1, bool DOTANH>
__global__ __launch_bounds__(256) void gemm_kt_kernel(
    const float* __restrict__ X1, const float* __restrict__ X2,
    const float* __restrict__ W,  const float* __restrict__ bias,
    float* __restrict__ out, int ldo)
{
    constexpr int NOUT = NVW*NBW;
    int w = threadIdx.x >> 5, lane = threadIdx.x & 31;
    int vbase = blockIdx.y*(8*NVW) + w*NVW;
    int bbase = blockIdx.x*NBW;

    float acc[NOUT];
    #pragma unroll
    for (int i = 0; i < NOUT; i++) acc[i] = 0.f;

    constexpr int CH = KTOT/128;
    #pragma unroll 2
    for (int c = 0; c < CH; c++) {
        int k = c*128 + lane*4;
        float4 xv[NBW];
        #pragma unroll
        for (int jb = 0; jb < NBW; jb++) {
            const float* src = (k < K1)
                ? (X1 + (size_t)(bbase+jb)*K1 + k)
                : (X2 + (size_t)(bbase+jb)*(KTOT-K1) + (k - K1));
            xv[jb] = *(const float4*)src;
        }
        #pragma unroll
        for (int iv = 0; iv < NVW; iv++) {
            float4 wv = *(const float4*)(W + (size_t)(vbase+iv)*KTOT + k);
            #pragma unroll
            for (int jb = 0; jb < NBW; jb++) {
                acc[iv*NBW + jb] += wv.x*xv[jb].x + wv.y*xv[jb].y
                                  + wv.z*xv[jb].z + wv.w*xv[jb].w;
            }
        }
    }

    __shared__ float red[8][32][33];
    #pragma unroll
    for (int g = 0; g < NOUT; g += 32) {
        __syncwarp();
        #pragma unroll
        for (int i = 0; i < 32; i++)
            red[w][i][lane] = acc[g + i];
        __syncwarp();
        float s = 0.f;
        #pragma unroll
        for (int l = 0; l < 32; l++)
            s += red[w][lane][l];
        int oi = g + lane;
        int vi = oi / NBW, jb = oi % NBW;
        int v = vbase + vi;
        float val = s + bias[v];
        if (DOTANH) val = __uint_as_float(f2tf32(tanhf(val)));
        out[(size_t)(bbase+jb)*ldo + v] = val;
    }
}

// ---------------- logits GEMM via mma.sync tf32 ----------------
// C[m][v] = cc[m][:]·Wo[v][:] + bo[v]; CTA tile 128m x 256v; warp 64x64.
// smem: As[2][128][36], Bs[2][256][36] (uint32 tf32 bits), cp.async pipelined.
#define LG_SMEM ((2*128*36 + 2*256*36)*4)
__global__ __launch_bounds__(256) void logits_mma(
    const float* __restrict__ cc,   // [2048][1024] tf32-rounded
    const float* __restrict__ wo,   // [32000][1024] tf32-rounded
    const float* __restrict__ bo,
    float* __restrict__ out)
{
    extern __shared__ uint32_t sm[];
    uint32_t* As = sm;                    // [2][128][36]
    uint32_t* Bs = sm + 2*128*36;         // [2][256][36]

    int tid = threadIdx.x, w = tid >> 5, lane = tid & 31;
    int g = lane >> 2, t4 = lane & 3;
    int warpM = w & 1, warpN = w >> 1;
    int mb = blockIdx.x * 128;            // cc rows
    int vb = blockIdx.y * 256;            // vocab rows

    const float* Ag = cc + (size_t)mb*HSZ;
    const float* Bg = wo + (size_t)vb*HSZ;
    uint32_t as_s = (uint32_t)__cvta_generic_to_shared(As);
    uint32_t bs_s = (uint32_t)__cvta_generic_to_shared(Bs);

    float acc[4][8][4];
    #pragma unroll
    for (int i = 0; i < 4; i++)
        #pragma unroll
        for (int jj = 0; jj < 8; jj++)
            #pragma unroll
            for (int k = 0; k < 4; k++) acc[i][jj][k] = 0.f;

    // issue chunk 0
    {
        int kc0 = 0;
        #pragma unroll
        for (int i = 0; i < 4; i++) {
            int idx = tid + i*256, r = idx >> 3, c = (idx & 7)*4;
            cp16(as_s + (r*36 + c)*4, Ag + (size_t)r*HSZ + kc0 + c);
        }
        #pragma unroll
        for (int i = 0; i < 8; i++) {
            int idx = tid + i*256, r = idx >> 3, c = (idx & 7)*4;
            cp16(bs_s + (r*36 + c)*4, Bg + (size_t)r*HSZ + kc0 + c);
        }
        CP_COMMIT();
    }

    for (int ch = 0; ch < 32; ch++) {
        if (ch < 31) {
            int kc0 = (ch+1)*32, buf = (ch+1) & 1;
            uint32_t ao = as_s + buf*128*36*4;
            uint32_t bo_s = bs_s + buf*256*36*4;
            #pragma unroll
            for (int i = 0; i < 4; i++) {
                int idx = tid + i*256, r = idx >> 3, c = (idx & 7)*4;
                cp16(ao + (r*36 + c)*4, Ag + (size_t)r*HSZ + kc0 + c);
            }
            #pragma unroll
            for (int i = 0; i < 8; i++) {
                int idx = tid + i*256, r = idx >> 3, c = (idx & 7)*4;
                cp16(bo_s + (r*36 + c)*4, Bg + (size_t)r*HSZ + kc0 + c);
            }
            CP_COMMIT();
            CP_WAIT(1);
        } else {
            CP_WAIT(0);
        }
        __syncthreads();

        int buf = ch & 1;
        const uint32_t* A0 = As + buf*128*36 + (warpM*64 + g)*36;
        const uint32_t* B0 = Bs + buf*256*36 + (warpN*64 + g)*36;

        #pragma unroll
        for (int ks = 0; ks < 4; ks++) {
            uint32_t a[4][4], b[8][2];
            #pragma unroll
            for (int mf = 0; mf < 4; mf++) {
                const uint32_t* ap = A0 + mf*16*36 + ks*8 + t4;
                a[mf][0] = ap[0];
                a[mf][1] = ap[8*36];
                a[mf][2] = ap[4];
                a[mf][3] = ap[8*36 + 4];
            }
            #pragma unroll
            for (int nf = 0; nf < 8; nf++) {
                const uint32_t* bp = B0 + nf*8*36 + ks*8 + t4;
                b[nf][0] = bp[0];
                b[nf][1] = bp[4];
            }
            #pragma unroll
            for (int mf = 0; mf < 4; mf++)
                #pragma unroll
                for (int nf = 0; nf < 8; nf++)
                    mma_tf32(acc[mf][nf], a[mf], b[nf]);
        }
        __syncthreads();
    }

    // epilogue
    #pragma unroll
    for (int nf = 0; nf < 8; nf++) {
        int v = vb + warpN*64 + nf*8 + t4*2;
        float b0v = bo[v], b1v = bo[v+1];
        #pragma unroll
        for (int mf = 0; mf < 4; mf++) {
            int m_lo = mb + warpM*64 + mf*16 + g;
            int m_hi = m_lo + 8;
            if (m_lo < (TSZ-1)*BSZ) {
                out[(size_t)(m_lo + BSZ)*VSZ + v    ] = acc[mf][nf][0] + b0v;
                out[(size_t)(m_lo + BSZ)*VSZ + v + 1] = acc[mf][nf][1] + b1v;
            }
            if (m_hi < (TSZ-1)*BSZ) {
                out[(size_t)(m_hi + BSZ)*VSZ + v    ] = acc[mf][nf][2] + b0v;
                out[(size_t)(m_hi + BSZ)*VSZ + v + 1] = acc[mf][nf][3] + b1v;
            }
        }
    }
}

// ---------------- host ----------------
extern "C" void kernel_launch(void* const* d_in, const int* in_sizes, int n_in,
                              void* d_out, int out_size) {
    const int*   src_tokens = (const int*)  d_in[0];
    const int*   tgt_tokens = (const int*)  d_in[1];
    const float* enc_emb    = (const float*)d_in[2];
    const float* enc_Wih0   = (const float*)d_in[3];
    const float* enc_Whh0   = (const float*)d_in[4];
    const float* enc_bih0   = (const float*)d_in[5];
    const float* enc_bhh0   = (const float*)d_in[6];
    const float* enc_Wih1   = (const float*)d_in[7];
    const float* enc_Whh1   = (const float*)d_in[8];
    const float* enc_bih1   = (const float*)d_in[9];
    const float* enc_bhh1   = (const float*)d_in[10];
    const float* dec_emb    = (const float*)d_in[11];
    const float* dec_Wih0   = (const float*)d_in[12];
    const float* dec_Whh0   = (const float*)d_in[13];
    const float* dec_bih0   = (const float*)d_in[14];
    const float* dec_bhh0   = (const float*)d_in[15];
    const float* dec_Wih1   = (const float*)d_in[16];
    const float* dec_Whh1   = (const float*)d_in[17];
    const float* dec_bih1   = (const float*)d_in[18];
    const float* dec_bhh1   = (const float*)d_in[19];
    const float* Wc         = (const float*)d_in[20];
    const float* bc         = (const float*)d_in[21];
    const float* Wo         = (const float*)d_in[22];
    const float* bo         = (const float*)d_in[23];
    float* out = (float*)d_out;

    float *emb_src, *emb_dec, *gx_enc, *gx_dec;
    float *enc_out_t, *h0, *h1, *dh0, *dh1, *h1t, *ctx_t, *cc_all, *wo_tf;
    cudaGetSymbolAddress((void**)&emb_src,   g_emb_src);
    cudaGetSymbolAddress((void**)&emb_dec,   g_emb_dec);
    cudaGetSymbolAddress((void**)&gx_enc,    g_gx_enc);
    cudaGetSymbolAddress((void**)&gx_dec,    g_gx_dec);
    cudaGetSymbolAddress((void**)&enc_out_t, g_enc_out_t);
    cudaGetSymbolAddress((void**)&h0,        g_h0);
    cudaGetSymbolAddress((void**)&h1,        g_h1);
    cudaGetSymbolAddress((void**)&dh0,       g_dh0);
    cudaGetSymbolAddress((void**)&dh1,       g_dh1);
    cudaGetSymbolAddress((void**)&h1t,       g_h1t);
    cudaGetSymbolAddress((void**)&ctx_t,     g_ctx_t);
    cudaGetSymbolAddress((void**)&cc_all,    g_cc_all);
    cudaGetSymbolAddress((void**)&wo_tf,     g_wo_tf);

    cudaFuncSetAttribute(gru_l1, cudaFuncAttributeMaxDynamicSharedMemorySize, L1_SMEM);
    cudaFuncSetAttribute(logits_mma, cudaFuncAttributeMaxDynamicSharedMemorySize, LG_SMEM);

    // 1: out rows 0..31 = zeros
    zero_kernel<<<1024, 256>>>(out, BSZ*VSZ);
    // 2: initial hiddens
    zero_h2_kernel<<<(2*HB)/256, 256>>>(h0, h1);
    // 3,4: embeddings
    embed_kernel<<<(SSZ*BSZ*ESZ)/256, 256>>>(src_tokens, enc_emb, emb_src, SSZ*BSZ);
    embed_kernel<<<((TSZ-1)*BSZ*ESZ)/256, 256>>>(tgt_tokens, dec_emb, emb_dec, (TSZ-1)*BSZ);
    // 5: encoder input projection
    proj_gemm<<<dim3(32, 48), 256>>>(emb_src, enc_Wih0, enc_bih0, gx_enc);

    // ---- encoder ---- (launch #6 = first gru_l0)
    for (int t = 0; t < SSZ; t++) {
        int rp = t & 1, wp = rp ^ 1;
        gru_l0<<<256, 256>>>(gx_enc + (size_t)t*3*HSZ*BSZ,
                             h0 + rp*HB, enc_Whh0, enc_bhh0, h0 + wp*HB);
        gru_l1<<<256, 256, L1_SMEM>>>(h0 + wp*HB, h1 + rp*HB,
                             enc_Wih1, enc_bih1, enc_Whh1, enc_bhh1,
                             h1 + wp*HB, nullptr,
                             enc_out_t + (size_t)t*BSZ*HSZ);
    }

    // decoder input projection
    proj_gemm<<<dim3(32, 48), 256>>>(emb_dec, dec_Wih0, dec_bih0, gx_dec);

    // ---- decoder ----
    for (int t = 0; t < TSZ-1; t++) {
        int wp = (t+1) & 1, rp = t & 1;
        const float* h0r = (t == 0) ? h0 : dh0 + rp*HB;
        const float* h1r = (t == 0) ? h1 : dh1 + rp*HB;

        gru_l0<<<256, 256>>>(gx_dec + (size_t)t*3*HSZ*BSZ,
                             h0r, dec_Whh0, dec_bhh0, dh0 + wp*HB);
        gru_l1<<<256, 256, L1_SMEM>>>(dh0 + wp*HB, h1r,
                             dec_Wih1, dec_bih1, dec_Whh1, dec_bhh1,
                             dh1 + wp*HB, h1t, nullptr);

        attn_kernel<<<BSZ, 256>>>(h1t, enc_out_t, src_tokens, ctx_t);

        gemm_kt_kernel<4, 8, 2*HSZ, HSZ, true><<<dim3(4, 32), 256>>>(
            h1t, ctx_t, Wc, bc, cc_all + (size_t)t*BSZ*HSZ, HSZ);
    }

    // convert Wo to tf32 bits, then one batched logits GEMM
    cvt_tf32_kernel<<<(VSZ*HSZ/4)/256, 256>>>(Wo, wo_tf);
    logits_mma<<<dim3(16, 125), 256, LG_SMEM>>>(cc_all, wo_tf, bo, out);
}